// round 16
// baseline (speedup 1.0000x reference)
#include <cuda_runtime.h>

#define B_   8
#define SQ_  2048
#define SK_  2048
#define DM_  1024
#define E_   128

// Scratch for projected Q (pre-scaled by 1/sqrt(128)), K, V — tf32-rounded fp32.
__device__ float g_Q[B_ * SQ_ * E_];
__device__ float g_K[B_ * SK_ * E_];
__device__ float g_V[B_ * SK_ * E_];

__device__ __forceinline__ unsigned f2tf32(float x) {
    unsigned r;
    asm("cvt.rna.tf32.f32 %0, %1;" : "=r"(r) : "f"(x));
    return r;
}

__device__ __forceinline__ void mma_tf32(float c[4], const unsigned a[4], const unsigned b[2]) {
    asm volatile(
        "mma.sync.aligned.m16n8k8.row.col.f32.tf32.tf32.f32 "
        "{%0,%1,%2,%3}, {%4,%5,%6,%7}, {%8,%9}, {%0,%1,%2,%3};\n"
        : "+f"(c[0]), "+f"(c[1]), "+f"(c[2]), "+f"(c[3])
        : "r"(a[0]), "r"(a[1]), "r"(a[2]), "r"(a[3]), "r"(b[0]), "r"(b[1]));
}

// ============================================================================
// Kernel 1: projection GEMM.  C[16384,128] = A[16384,1024] @ W[1024,128] + bias
// blockIdx.y selects (queries,w_q)->g_Q (scaled), (keys,w_k)->g_K, (values,w_v)->g_V
// CTA tile 128x128, k-tile 32, 8 warps (4M x 2N), warp tile 32x64, TF32 mma.
// ============================================================================
__global__ __launch_bounds__(256) void proj_kernel(
    const float* __restrict__ q, const float* __restrict__ k, const float* __restrict__ v,
    const float* __restrict__ wq, const float* __restrict__ bq,
    const float* __restrict__ wk, const float* __restrict__ bk,
    const float* __restrict__ wv, const float* __restrict__ bv)
{
    __shared__ float As[128][36];   // pad 36: frag-load bank = laneid (conflict-free)
    __shared__ float Ws[32][136];   // pad 136: frag-load bank = laneid

    const float* A; const float* W; const float* bias; float* C; float scale;
    if (blockIdx.y == 0)      { A = q; W = wq; bias = bq; C = g_Q; scale = 0.088388347648318447f; }
    else if (blockIdx.y == 1) { A = k; W = wk; bias = bk; C = g_K; scale = 1.0f; }
    else                      { A = v; W = wv; bias = bv; C = g_V; scale = 1.0f; }

    const int tid  = threadIdx.x;
    const int lane = tid & 31;
    const int w    = tid >> 5;
    const int wm   = (w >> 1) * 32;   // 0,32,64,96
    const int wn   = (w & 1) * 64;    // 0,64
    const int m0   = blockIdx.x * 128;

    float acc[2][8][4];
#pragma unroll
    for (int i = 0; i < 2; i++)
#pragma unroll
        for (int j = 0; j < 8; j++)
#pragma unroll
            for (int t = 0; t < 4; t++) acc[i][j][t] = 0.f;

    for (int kk = 0; kk < DM_; kk += 32) {
        // load A tile 128x32 (1024 float4, 4 per thread), tf32-round into smem
#pragma unroll
        for (int i = 0; i < 4; i++) {
            int linear = tid + i * 256;
            int r = linear >> 3, c4 = linear & 7;
            float4 val = *reinterpret_cast<const float4*>(&A[(size_t)(m0 + r) * DM_ + kk + c4 * 4]);
            As[r][c4 * 4 + 0] = __uint_as_float(f2tf32(val.x));
            As[r][c4 * 4 + 1] = __uint_as_float(f2tf32(val.y));
            As[r][c4 * 4 + 2] = __uint_as_float(f2tf32(val.z));
            As[r][c4 * 4 + 3] = __uint_as_float(f2tf32(val.w));
        }
        // load W tile 32x128
#pragma unroll
        for (int i = 0; i < 4; i++) {
            int linear = tid + i * 256;
            int r = linear >> 5, c4 = linear & 31;
            float4 val = *reinterpret_cast<const float4*>(&W[(size_t)(kk + r) * E_ + c4 * 4]);
            Ws[r][c4 * 4 + 0] = __uint_as_float(f2tf32(val.x));
            Ws[r][c4 * 4 + 1] = __uint_as_float(f2tf32(val.y));
            Ws[r][c4 * 4 + 2] = __uint_as_float(f2tf32(val.z));
            Ws[r][c4 * 4 + 3] = __uint_as_float(f2tf32(val.w));
        }
        __syncthreads();

#pragma unroll
        for (int ks = 0; ks < 4; ks++) {
            const int k8 = ks * 8;
            unsigned a[2][4], bfr[8][2];
#pragma unroll
            for (int mi = 0; mi < 2; mi++) {
                int r = wm + mi * 16 + (lane >> 2);
                int c = k8 + (lane & 3);
                a[mi][0] = __float_as_uint(As[r][c]);
                a[mi][1] = __float_as_uint(As[r + 8][c]);
                a[mi][2] = __float_as_uint(As[r][c + 4]);
                a[mi][3] = __float_as_uint(As[r + 8][c + 4]);
            }
#pragma unroll
            for (int ni = 0; ni < 8; ni++) {
                int n = wn + ni * 8 + (lane >> 2);
                bfr[ni][0] = __float_as_uint(Ws[k8 + (lane & 3)][n]);
                bfr[ni][1] = __float_as_uint(Ws[k8 + (lane & 3) + 4][n]);
            }
#pragma unroll
            for (int mi = 0; mi < 2; mi++)
#pragma unroll
                for (int ni = 0; ni < 8; ni++)
                    mma_tf32(acc[mi][ni], a[mi], bfr[ni]);
        }
        __syncthreads();
    }

    // epilogue: +bias, *scale, tf32-round, store
#pragma unroll
    for (int mi = 0; mi < 2; mi++) {
        int r0 = m0 + wm + mi * 16 + (lane >> 2);
#pragma unroll
        for (int ni = 0; ni < 8; ni++) {
            int c0 = wn + ni * 8 + (lane & 3) * 2;
            C[(size_t)r0 * E_ + c0]           = __uint_as_float(f2tf32((acc[mi][ni][0] + bias[c0])     * scale));
            C[(size_t)r0 * E_ + c0 + 1]       = __uint_as_float(f2tf32((acc[mi][ni][1] + bias[c0 + 1]) * scale));
            C[(size_t)(r0 + 8) * E_ + c0]     = __uint_as_float(f2tf32((acc[mi][ni][2] + bias[c0])     * scale));
            C[(size_t)(r0 + 8) * E_ + c0 + 1] = __uint_as_float(f2tf32((acc[mi][ni][3] + bias[c0 + 1]) * scale));
        }
    }
}

// ============================================================================
// Kernel 2: flash attention over g_Q/g_K/g_V with key-length mask.
// CTA: 64 q-rows x E=128, 4 warps (16 rows each -> softmax reductions in-quad).
// Key loop truncated at ceil(valid/64): masked keys have exactly-zero weight.
// ============================================================================
#define TQ  64
#define TK  64
#define LDQ 132
#define LDK 132
#define LDV 136
#define LDP 68
#define ATTN_SMEM ((TQ*LDQ + TK*LDK + TK*LDV + TQ*LDP) * 4)

__global__ __launch_bounds__(128) void attn_kernel(const int* __restrict__ valid_lens,
                                                   float* __restrict__ out)
{
    extern __shared__ float sm[];
    float* Qs = sm;                   // [64][132]
    float* Ks = Qs + TQ * LDQ;        // [64][132]
    float* Vs = Ks + TK * LDK;        // [64][136]
    float* Ps = Vs + TK * LDV;        // [64][68]

    const int tid  = threadIdx.x;
    const int lane = tid & 31;
    const int warp = tid >> 5;
    const int b    = blockIdx.y;
    const int q0   = blockIdx.x * TQ;
    const int valid = valid_lens[b];

    const float* Qg = g_Q + ((size_t)b * SQ_ + q0) * E_;
    const float* Kg = g_K + (size_t)b * SK_ * E_;
    const float* Vg = g_V + (size_t)b * SK_ * E_;

    // load Q tile 64x128 (2048 float4, 16 per thread)
#pragma unroll
    for (int i = 0; i < 16; i++) {
        int linear = tid + i * 128;
        int r = linear >> 5, c4 = linear & 31;
        float4 val = *reinterpret_cast<const float4*>(&Qg[(size_t)r * E_ + c4 * 4]);
        Qs[r * LDQ + c4 * 4 + 0] = val.x;
        Qs[r * LDQ + c4 * 4 + 1] = val.y;
        Qs[r * LDQ + c4 * 4 + 2] = val.z;
        Qs[r * LDQ + c4 * 4 + 3] = val.w;
    }

    float o[16][4];
#pragma unroll
    for (int n = 0; n < 16; n++)
#pragma unroll
        for (int j = 0; j < 4; j++) o[n][j] = 0.f;
    float m_i[2] = {-1e30f, -1e30f};
    float l_i[2] = {0.f, 0.f};

    const int rowA   = warp * 16 + (lane >> 2);
    const int ntiles = (valid + TK - 1) / TK;

    for (int t = 0; t < ntiles; t++) {
        const int kb = t * TK;
        __syncthreads();   // prior P@V done (and t=0: Q loads visible) before overwriting K/V
        // load K,V tiles (64x128 each)
#pragma unroll
        for (int i = 0; i < 16; i++) {
            int linear = tid + i * 128;
            int r = linear >> 5, c4 = linear & 31;
            float4 kv = *reinterpret_cast<const float4*>(&Kg[(size_t)(kb + r) * E_ + c4 * 4]);
            Ks[r * LDK + c4 * 4 + 0] = kv.x;
            Ks[r * LDK + c4 * 4 + 1] = kv.y;
            Ks[r * LDK + c4 * 4 + 2] = kv.z;
            Ks[r * LDK + c4 * 4 + 3] = kv.w;
            float4 vv = *reinterpret_cast<const float4*>(&Vg[(size_t)(kb + r) * E_ + c4 * 4]);
            Vs[r * LDV + c4 * 4 + 0] = vv.x;
            Vs[r * LDV + c4 * 4 + 1] = vv.y;
            Vs[r * LDV + c4 * 4 + 2] = vv.z;
            Vs[r * LDV + c4 * 4 + 3] = vv.w;
        }
        __syncthreads();

        // S = Q @ K^T   (Q pre-scaled by 1/sqrt(128))
        float s[8][4];
#pragma unroll
        for (int n = 0; n < 8; n++)
#pragma unroll
            for (int j = 0; j < 4; j++) s[n][j] = 0.f;
#pragma unroll
        for (int ks = 0; ks < 16; ks++) {
            const int k8 = ks * 8;
            unsigned a[4];
            a[0] = __float_as_uint(Qs[rowA * LDQ + k8 + (lane & 3)]);
            a[1] = __float_as_uint(Qs[(rowA + 8) * LDQ + k8 + (lane & 3)]);
            a[2] = __float_as_uint(Qs[rowA * LDQ + k8 + (lane & 3) + 4]);
            a[3] = __float_as_uint(Qs[(rowA + 8) * LDQ + k8 + (lane & 3) + 4]);
#pragma unroll
            for (int nt = 0; nt < 8; nt++) {
                unsigned bb[2];
                int n = nt * 8 + (lane >> 2);
                bb[0] = __float_as_uint(Ks[n * LDK + k8 + (lane & 3)]);
                bb[1] = __float_as_uint(Ks[n * LDK + k8 + (lane & 3) + 4]);
                mma_tf32(s[nt], a, bb);
            }
        }

        // mask in the boundary tile
        if (kb + TK > valid) {
#pragma unroll
            for (int nt = 0; nt < 8; nt++) {
                int c = kb + nt * 8 + (lane & 3) * 2;
                if (c >= valid)     { s[nt][0] = -1e30f; s[nt][2] = -1e30f; }
                if (c + 1 >= valid) { s[nt][1] = -1e30f; s[nt][3] = -1e30f; }
            }
        }

        // row max (rows rowA, rowA+8) — reduce 16 cols/thread then within quad
        float tm0 = -1e30f, tm1 = -1e30f;
#pragma unroll
        for (int nt = 0; nt < 8; nt++) {
            tm0 = fmaxf(tm0, fmaxf(s[nt][0], s[nt][1]));
            tm1 = fmaxf(tm1, fmaxf(s[nt][2], s[nt][3]));
        }
#pragma unroll
        for (int off = 1; off < 4; off <<= 1) {
            tm0 = fmaxf(tm0, __shfl_xor_sync(0xffffffffu, tm0, off));
            tm1 = fmaxf(tm1, __shfl_xor_sync(0xffffffffu, tm1, off));
        }
        float mn0 = fmaxf(m_i[0], tm0);
        float mn1 = fmaxf(m_i[1], tm1);
        float alpha0 = __expf(m_i[0] - mn0);
        float alpha1 = __expf(m_i[1] - mn1);
        m_i[0] = mn0; m_i[1] = mn1;

        float rs0 = 0.f, rs1 = 0.f;
#pragma unroll
        for (int nt = 0; nt < 8; nt++) {
            s[nt][0] = __expf(s[nt][0] - mn0);
            s[nt][1] = __expf(s[nt][1] - mn0);
            s[nt][2] = __expf(s[nt][2] - mn1);
            s[nt][3] = __expf(s[nt][3] - mn1);
            rs0 += s[nt][0] + s[nt][1];
            rs1 += s[nt][2] + s[nt][3];
        }
#pragma unroll
        for (int off = 1; off < 4; off <<= 1) {
            rs0 += __shfl_xor_sync(0xffffffffu, rs0, off);
            rs1 += __shfl_xor_sync(0xffffffffu, rs1, off);
        }
        l_i[0] = l_i[0] * alpha0 + rs0;
        l_i[1] = l_i[1] * alpha1 + rs1;

#pragma unroll
        for (int n = 0; n < 16; n++) {
            o[n][0] *= alpha0; o[n][1] *= alpha0;
            o[n][2] *= alpha1; o[n][3] *= alpha1;
        }

        // P -> smem (C-frag layout -> A-frag layout round-trip, warp-private rows)
#pragma unroll
        for (int nt = 0; nt < 8; nt++) {
            int c = nt * 8 + (lane & 3) * 2;
            Ps[rowA * LDP + c]           = __uint_as_float(f2tf32(s[nt][0]));
            Ps[rowA * LDP + c + 1]       = __uint_as_float(f2tf32(s[nt][1]));
            Ps[(rowA + 8) * LDP + c]     = __uint_as_float(f2tf32(s[nt][2]));
            Ps[(rowA + 8) * LDP + c + 1] = __uint_as_float(f2tf32(s[nt][3]));
        }
        __syncwarp();

        // O += P @ V
#pragma unroll
        for (int ks = 0; ks < 8; ks++) {
            const int k8 = ks * 8;
            unsigned a[4];
            a[0] = __float_as_uint(Ps[rowA * LDP + k8 + (lane & 3)]);
            a[1] = __float_as_uint(Ps[(rowA + 8) * LDP + k8 + (lane & 3)]);
            a[2] = __float_as_uint(Ps[rowA * LDP + k8 + (lane & 3) + 4]);
            a[3] = __float_as_uint(Ps[(rowA + 8) * LDP + k8 + (lane & 3) + 4]);
#pragma unroll
            for (int nt = 0; nt < 16; nt++) {
                unsigned bb[2];
                int n = nt * 8 + (lane >> 2);
                bb[0] = __float_as_uint(Vs[(k8 + (lane & 3)) * LDV + n]);
                bb[1] = __float_as_uint(Vs[(k8 + (lane & 3) + 4) * LDV + n]);
                mma_tf32(o[nt], a, bb);
            }
        }
    }

    // epilogue: divide by l, write out
    float inv0 = 1.f / l_i[0];
    float inv1 = 1.f / l_i[1];
    float* outg = out + ((size_t)b * SQ_ + q0) * E_;
#pragma unroll
    for (int nt = 0; nt < 16; nt++) {
        int c = nt * 8 + (lane & 3) * 2;
        outg[(size_t)rowA * E_ + c]           = o[nt][0] * inv0;
        outg[(size_t)rowA * E_ + c + 1]       = o[nt][1] * inv0;
        outg[(size_t)(rowA + 8) * E_ + c]     = o[nt][2] * inv1;
        outg[(size_t)(rowA + 8) * E_ + c + 1] = o[nt][3] * inv1;
    }
}

extern "C" void kernel_launch(void* const* d_in, const int* in_sizes, int n_in,
                              void* d_out, int out_size)
{
    (void)in_sizes; (void)n_in; (void)out_size;
    const float* q  = (const float*)d_in[0];
    const float* k  = (const float*)d_in[1];
    const float* v  = (const float*)d_in[2];
    const int*   vl = (const int*)d_in[3];
    const float* wq = (const float*)d_in[4];
    const float* bq = (const float*)d_in[5];
    const float* wk = (const float*)d_in[6];
    const float* bk = (const float*)d_in[7];
    const float* wv = (const float*)d_in[8];
    const float* bv = (const float*)d_in[9];

    proj_kernel<<<dim3(128, 3), 256>>>(q, k, v, wq, bq, wk, bk, wv, bv);

    cudaFuncSetAttribute(attn_kernel, cudaFuncAttributeMaxDynamicSharedMemorySize, ATTN_SMEM);
    attn_kernel<<<dim3(SQ_ / TQ, B_), 128, ATTN_SMEM>>>(vl, (float*)d_out);
}

// round 17
// speedup vs baseline: 1.1812x; 1.1812x over previous
#include <cuda_runtime.h>

#define B_   8
#define SQ_  2048
#define SK_  2048
#define DM_  1024
#define E_   128

// Scratch for projected Q (pre-scaled by 1/sqrt(128)), K, V — tf32-rounded fp32.
__device__ float g_Q[B_ * SQ_ * E_];
__device__ float g_K[B_ * SK_ * E_];
__device__ float g_V[B_ * SK_ * E_];

__device__ __forceinline__ unsigned f2tf32(float x) {
    unsigned r;
    asm("cvt.rna.tf32.f32 %0, %1;" : "=r"(r) : "f"(x));
    return r;
}

__device__ __forceinline__ void mma_tf32(float c[4], const unsigned a[4], const unsigned b[2]) {
    asm volatile(
        "mma.sync.aligned.m16n8k8.row.col.f32.tf32.tf32.f32 "
        "{%0,%1,%2,%3}, {%4,%5,%6,%7}, {%8,%9}, {%0,%1,%2,%3};\n"
        : "+f"(c[0]), "+f"(c[1]), "+f"(c[2]), "+f"(c[3])
        : "r"(a[0]), "r"(a[1]), "r"(a[2]), "r"(a[3]), "r"(b[0]), "r"(b[1]));
}

// ============================================================================
// Kernel 1: projection GEMM.  C[16384,128] = A[16384,1024] @ W[1024,128] + bias
// Register-prefetch ping-pong: next k-tile's LDGs issued before compute of the
// current tile, so the 577-cyc DRAM latency hides behind 512 MMAs per CTA.
// ============================================================================
__global__ __launch_bounds__(256) void proj_kernel(
    const float* __restrict__ q, const float* __restrict__ k, const float* __restrict__ v,
    const float* __restrict__ wq, const float* __restrict__ bq,
    const float* __restrict__ wk, const float* __restrict__ bk,
    const float* __restrict__ wv, const float* __restrict__ bv)
{
    __shared__ float As[128][36];   // pad 36: frag-load bank = laneid (conflict-free)
    __shared__ float Ws[32][136];   // pad 136: frag-load bank = laneid

    const float* A; const float* W; const float* bias; float* C; float scale;
    if (blockIdx.y == 0)      { A = q; W = wq; bias = bq; C = g_Q; scale = 0.088388347648318447f; }
    else if (blockIdx.y == 1) { A = k; W = wk; bias = bk; C = g_K; scale = 1.0f; }
    else                      { A = v; W = wv; bias = bv; C = g_V; scale = 1.0f; }

    const int tid  = threadIdx.x;
    const int lane = tid & 31;
    const int w    = tid >> 5;
    const int wm   = (w >> 1) * 32;   // 0,32,64,96
    const int wn   = (w & 1) * 64;    // 0,64
    const int m0   = blockIdx.x * 128;

    float acc[2][8][4];
#pragma unroll
    for (int i = 0; i < 2; i++)
#pragma unroll
        for (int j = 0; j < 8; j++)
#pragma unroll
            for (int t = 0; t < 4; t++) acc[i][j][t] = 0.f;

    float4 pa[4], pw[4];
    // prologue: prefetch k-tile 0
#pragma unroll
    for (int i = 0; i < 4; i++) {
        int linear = tid + i * 256;
        int r = linear >> 3, c4 = linear & 7;
        pa[i] = *reinterpret_cast<const float4*>(&A[(size_t)(m0 + r) * DM_ + c4 * 4]);
        int rw = linear >> 5, cw = linear & 31;
        pw[i] = *reinterpret_cast<const float4*>(&W[(size_t)rw * E_ + cw * 4]);
    }

    for (int t = 0; t < DM_ / 32; t++) {
        // store prefetched tile to smem (tf32-rounded)
#pragma unroll
        for (int i = 0; i < 4; i++) {
            int linear = tid + i * 256;
            int r = linear >> 3, c4 = linear & 7;
            As[r][c4 * 4 + 0] = __uint_as_float(f2tf32(pa[i].x));
            As[r][c4 * 4 + 1] = __uint_as_float(f2tf32(pa[i].y));
            As[r][c4 * 4 + 2] = __uint_as_float(f2tf32(pa[i].z));
            As[r][c4 * 4 + 3] = __uint_as_float(f2tf32(pa[i].w));
            int rw = linear >> 5, cw = linear & 31;
            Ws[rw][cw * 4 + 0] = __uint_as_float(f2tf32(pw[i].x));
            Ws[rw][cw * 4 + 1] = __uint_as_float(f2tf32(pw[i].y));
            Ws[rw][cw * 4 + 2] = __uint_as_float(f2tf32(pw[i].z));
            Ws[rw][cw * 4 + 3] = __uint_as_float(f2tf32(pw[i].w));
        }
        __syncthreads();

        // prefetch next k-tile (LDGs issued before compute, consumed next iter)
        if (t + 1 < DM_ / 32) {
            int kk2 = (t + 1) * 32;
#pragma unroll
            for (int i = 0; i < 4; i++) {
                int linear = tid + i * 256;
                int r = linear >> 3, c4 = linear & 7;
                pa[i] = *reinterpret_cast<const float4*>(&A[(size_t)(m0 + r) * DM_ + kk2 + c4 * 4]);
                int rw = linear >> 5, cw = linear & 31;
                pw[i] = *reinterpret_cast<const float4*>(&W[(size_t)(kk2 + rw) * E_ + cw * 4]);
            }
        }

#pragma unroll
        for (int ks = 0; ks < 4; ks++) {
            const int k8 = ks * 8;
            unsigned a[2][4], bfr[8][2];
#pragma unroll
            for (int mi = 0; mi < 2; mi++) {
                int r = wm + mi * 16 + (lane >> 2);
                int c = k8 + (lane & 3);
                a[mi][0] = __float_as_uint(As[r][c]);
                a[mi][1] = __float_as_uint(As[r + 8][c]);
                a[mi][2] = __float_as_uint(As[r][c + 4]);
                a[mi][3] = __float_as_uint(As[r + 8][c + 4]);
            }
#pragma unroll
            for (int ni = 0; ni < 8; ni++) {
                int n = wn + ni * 8 + (lane >> 2);
                bfr[ni][0] = __float_as_uint(Ws[k8 + (lane & 3)][n]);
                bfr[ni][1] = __float_as_uint(Ws[k8 + (lane & 3) + 4][n]);
            }
#pragma unroll
            for (int mi = 0; mi < 2; mi++)
#pragma unroll
                for (int ni = 0; ni < 8; ni++)
                    mma_tf32(acc[mi][ni], a[mi], bfr[ni]);
        }
        __syncthreads();
    }

    // epilogue: +bias, *scale, tf32-round, store
#pragma unroll
    for (int mi = 0; mi < 2; mi++) {
        int r0 = m0 + wm + mi * 16 + (lane >> 2);
#pragma unroll
        for (int ni = 0; ni < 8; ni++) {
            int c0 = wn + ni * 8 + (lane & 3) * 2;
            C[(size_t)r0 * E_ + c0]           = __uint_as_float(f2tf32((acc[mi][ni][0] + bias[c0])     * scale));
            C[(size_t)r0 * E_ + c0 + 1]       = __uint_as_float(f2tf32((acc[mi][ni][1] + bias[c0 + 1]) * scale));
            C[(size_t)(r0 + 8) * E_ + c0]     = __uint_as_float(f2tf32((acc[mi][ni][2] + bias[c0])     * scale));
            C[(size_t)(r0 + 8) * E_ + c0 + 1] = __uint_as_float(f2tf32((acc[mi][ni][3] + bias[c0 + 1]) * scale));
        }
    }
}

// ============================================================================
// Kernel 2: flash attention over g_Q/g_K/g_V with key-length mask.
// CTA: 64 q-rows x E=128, 4 warps (16 rows each -> softmax reductions in-quad).
// v2: Q fragments held in registers (loaded once via staging aliased on the K
// tile) -> smem 117KB -> 86KB -> 2 CTAs/SM (8 warps/SM), and 64 fewer LDS per
// tile. 1-D grid interleaves batches so co-resident CTAs average valid_lens.
// ============================================================================
#define TQ  64
#define TK  64
#define LDK 132
#define LDV 136
#define LDP 68
#define ATTN_SMEM ((TK*LDK + TK*LDV + TQ*LDP) * 4)   // 86016 B

__global__ __launch_bounds__(128, 2) void attn_kernel(const int* __restrict__ valid_lens,
                                                      float* __restrict__ out)
{
    extern __shared__ float sm[];
    float* Ks = sm;                   // [64][132]
    float* Vs = Ks + TK * LDK;        // [64][136]
    float* Ps = Vs + TK * LDV;        // [64][68]
    float* Qstage = sm;               // aliases Ks region (same 132 stride)

    const int tid  = threadIdx.x;
    const int lane = tid & 31;
    const int warp = tid >> 5;
    const int b    = blockIdx.x & 7;          // interleave batches across adjacent CTAs
    const int q0   = (blockIdx.x >> 3) * TQ;
    const int valid = valid_lens[b];

    const float* Qg = g_Q + ((size_t)b * SQ_ + q0) * E_;
    const float* Kg = g_K + (size_t)b * SK_ * E_;
    const float* Vg = g_V + (size_t)b * SK_ * E_;

    const int rowA = warp * 16 + (lane >> 2);
    const int qq   = lane & 3;

    // stage Q tile 64x128 into smem, then pull A-fragments into registers
#pragma unroll
    for (int i = 0; i < 16; i++) {
        int linear = tid + i * 128;
        int r = linear >> 5, c4 = linear & 31;
        float4 val = *reinterpret_cast<const float4*>(&Qg[(size_t)r * E_ + c4 * 4]);
        Qstage[r * LDK + c4 * 4 + 0] = val.x;
        Qstage[r * LDK + c4 * 4 + 1] = val.y;
        Qstage[r * LDK + c4 * 4 + 2] = val.z;
        Qstage[r * LDK + c4 * 4 + 3] = val.w;
    }
    __syncthreads();

    unsigned qf[16][4];
#pragma unroll
    for (int ks = 0; ks < 16; ks++) {
        const int k8 = ks * 8;
        qf[ks][0] = __float_as_uint(Qstage[rowA * LDK + k8 + qq]);
        qf[ks][1] = __float_as_uint(Qstage[(rowA + 8) * LDK + k8 + qq]);
        qf[ks][2] = __float_as_uint(Qstage[rowA * LDK + k8 + qq + 4]);
        qf[ks][3] = __float_as_uint(Qstage[(rowA + 8) * LDK + k8 + qq + 4]);
    }

    float o[16][4];
#pragma unroll
    for (int n = 0; n < 16; n++)
#pragma unroll
        for (int j = 0; j < 4; j++) o[n][j] = 0.f;
    float m_i[2] = {-1e30f, -1e30f};
    float l_i[2] = {0.f, 0.f};

    const int ntiles = (valid + TK - 1) / TK;

    for (int t = 0; t < ntiles; t++) {
        const int kb = t * TK;
        __syncthreads();   // t=0: qf reads done; t>0: prior P@V done, before K/V overwrite
        // load K,V tiles (64x128 each)
#pragma unroll
        for (int i = 0; i < 16; i++) {
            int linear = tid + i * 128;
            int r = linear >> 5, c4 = linear & 31;
            float4 kv = *reinterpret_cast<const float4*>(&Kg[(size_t)(kb + r) * E_ + c4 * 4]);
            Ks[r * LDK + c4 * 4 + 0] = kv.x;
            Ks[r * LDK + c4 * 4 + 1] = kv.y;
            Ks[r * LDK + c4 * 4 + 2] = kv.z;
            Ks[r * LDK + c4 * 4 + 3] = kv.w;
            float4 vv = *reinterpret_cast<const float4*>(&Vg[(size_t)(kb + r) * E_ + c4 * 4]);
            Vs[r * LDV + c4 * 4 + 0] = vv.x;
            Vs[r * LDV + c4 * 4 + 1] = vv.y;
            Vs[r * LDV + c4 * 4 + 2] = vv.z;
            Vs[r * LDV + c4 * 4 + 3] = vv.w;
        }
        __syncthreads();

        // S = Q @ K^T   (Q pre-scaled by 1/sqrt(128); A-frags already in regs)
        float s[8][4];
#pragma unroll
        for (int n = 0; n < 8; n++)
#pragma unroll
            for (int j = 0; j < 4; j++) s[n][j] = 0.f;
#pragma unroll
        for (int ks = 0; ks < 16; ks++) {
            const int k8 = ks * 8;
#pragma unroll
            for (int nt = 0; nt < 8; nt++) {
                unsigned bb[2];
                int n = nt * 8 + (lane >> 2);
                bb[0] = __float_as_uint(Ks[n * LDK + k8 + qq]);
                bb[1] = __float_as_uint(Ks[n * LDK + k8 + qq + 4]);
                mma_tf32(s[nt], qf[ks], bb);
            }
        }

        // mask in the boundary tile
        if (kb + TK > valid) {
#pragma unroll
            for (int nt = 0; nt < 8; nt++) {
                int c = kb + nt * 8 + qq * 2;
                if (c >= valid)     { s[nt][0] = -1e30f; s[nt][2] = -1e30f; }
                if (c + 1 >= valid) { s[nt][1] = -1e30f; s[nt][3] = -1e30f; }
            }
        }

        // row max (rows rowA, rowA+8) — reduce 16 cols/thread then within quad
        float tm0 = -1e30f, tm1 = -1e30f;
#pragma unroll
        for (int nt = 0; nt < 8; nt++) {
            tm0 = fmaxf(tm0, fmaxf(s[nt][0], s[nt][1]));
            tm1 = fmaxf(tm1, fmaxf(s[nt][2], s[nt][3]));
        }
#pragma unroll
        for (int off = 1; off < 4; off <<= 1) {
            tm0 = fmaxf(tm0, __shfl_xor_sync(0xffffffffu, tm0, off));
            tm1 = fmaxf(tm1, __shfl_xor_sync(0xffffffffu, tm1, off));
        }
        float mn0 = fmaxf(m_i[0], tm0);
        float mn1 = fmaxf(m_i[1], tm1);
        float alpha0 = __expf(m_i[0] - mn0);
        float alpha1 = __expf(m_i[1] - mn1);
        m_i[0] = mn0; m_i[1] = mn1;

        float rs0 = 0.f, rs1 = 0.f;
#pragma unroll
        for (int nt = 0; nt < 8; nt++) {
            s[nt][0] = __expf(s[nt][0] - mn0);
            s[nt][1] = __expf(s[nt][1] - mn0);
            s[nt][2] = __expf(s[nt][2] - mn1);
            s[nt][3] = __expf(s[nt][3] - mn1);
            rs0 += s[nt][0] + s[nt][1];
            rs1 += s[nt][2] + s[nt][3];
        }
#pragma unroll
        for (int off = 1; off < 4; off <<= 1) {
            rs0 += __shfl_xor_sync(0xffffffffu, rs0, off);
            rs1 += __shfl_xor_sync(0xffffffffu, rs1, off);
        }
        l_i[0] = l_i[0] * alpha0 + rs0;
        l_i[1] = l_i[1] * alpha1 + rs1;

#pragma unroll
        for (int n = 0; n < 16; n++) {
            o[n][0] *= alpha0; o[n][1] *= alpha0;
            o[n][2] *= alpha1; o[n][3] *= alpha1;
        }

        // P -> smem (C-frag layout -> A-frag layout round-trip, warp-private rows)
#pragma unroll
        for (int nt = 0; nt < 8; nt++) {
            int c = nt * 8 + qq * 2;
            Ps[rowA * LDP + c]           = __uint_as_float(f2tf32(s[nt][0]));
            Ps[rowA * LDP + c + 1]       = __uint_as_float(f2tf32(s[nt][1]));
            Ps[(rowA + 8) * LDP + c]     = __uint_as_float(f2tf32(s[nt][2]));
            Ps[(rowA + 8) * LDP + c + 1] = __uint_as_float(f2tf32(s[nt][3]));
        }
        __syncwarp();

        // O += P @ V
#pragma unroll
        for (int ks = 0; ks < 8; ks++) {
            const int k8 = ks * 8;
            unsigned a[4];
            a[0] = __float_as_uint(Ps[rowA * LDP + k8 + qq]);
            a[1] = __float_as_uint(Ps[(rowA + 8) * LDP + k8 + qq]);
            a[2] = __float_as_uint(Ps[rowA * LDP + k8 + qq + 4]);
            a[3] = __float_as_uint(Ps[(rowA + 8) * LDP + k8 + qq + 4]);
#pragma unroll
            for (int nt = 0; nt < 16; nt++) {
                unsigned bb[2];
                int n = nt * 8 + (lane >> 2);
                bb[0] = __float_as_uint(Vs[(k8 + qq) * LDV + n]);
                bb[1] = __float_as_uint(Vs[(k8 + qq + 4) * LDV + n]);
                mma_tf32(o[nt], a, bb);
            }
        }
    }

    // epilogue: divide by l, write out
    float inv0 = 1.f / l_i[0];
    float inv1 = 1.f / l_i[1];
    float* outg = out + ((size_t)b * SQ_ + q0) * E_;
#pragma unroll
    for (int nt = 0; nt < 16; nt++) {
        int c = nt * 8 + qq * 2;
        outg[(size_t)rowA * E_ + c]           = o[nt][0] * inv0;
        outg[(size_t)rowA * E_ + c + 1]       = o[nt][1] * inv0;
        outg[(size_t)(rowA + 8) * E_ + c]     = o[nt][2] * inv1;
        outg[(size_t)(rowA + 8) * E_ + c + 1] = o[nt][3] * inv1;
    }
}

extern "C" void kernel_launch(void* const* d_in, const int* in_sizes, int n_in,
                              void* d_out, int out_size)
{
    (void)in_sizes; (void)n_in; (void)out_size;
    const float* q  = (const float*)d_in[0];
    const float* k  = (const float*)d_in[1];
    const float* v  = (const float*)d_in[2];
    const int*   vl = (const int*)d_in[3];
    const float* wq = (const float*)d_in[4];
    const float* bq = (const float*)d_in[5];
    const float* wk = (const float*)d_in[6];
    const float* bk = (const float*)d_in[7];
    const float* wv = (const float*)d_in[8];
    const float* bv = (const float*)d_in[9];

    proj_kernel<<<dim3(128, 3), 256>>>(q, k, v, wq, bq, wk, bk, wv, bv);

    cudaFuncSetAttribute(attn_kernel, cudaFuncAttributeMaxDynamicSharedMemorySize, ATTN_SMEM);
    attn_kernel<<<dim3((SQ_ / TQ) * B_), 128, ATTN_SMEM>>>(vl, (float*)d_out);
}